// round 1
// baseline (speedup 1.0000x reference)
#include <cuda_runtime.h>
#include <cuda_bf16.h>
#include <cstdint>

#define N 8192
#define D 128
#define BM 128
#define BN 128
#define SSTRIDE 136                      // 128 + 8 bf16 pad -> conflict-free ldmatrix
#define SMEM_BYTES (2 * BM * SSTRIDE * 2)

// -------- device scratch (no allocations allowed) --------
__device__ __nv_bfloat16 g_zn[N * D];    // normalized nodes, bf16
__device__ float g_sumz[D];              // column sum of normalized nodes
__device__ float g_sumzp[D];             // column sum of normalized pair_nodes
__device__ float g_den[N];               // den_sum per row

// -------- kernel 0: zero scratch --------
__global__ void zero_kernel() {
    int i = blockIdx.x * blockDim.x + threadIdx.x;
    if (i < N) g_den[i] = 0.f;
    if (i < D) { g_sumz[i] = 0.f; g_sumzp[i] = 0.f; }
}

// -------- kernel 1: normalize rows, store bf16, accumulate column sums --------
__global__ void prep_kernel(const float* __restrict__ nodes,
                            const float* __restrict__ pairn) {
    __shared__ float s_col[D];
    int tid = threadIdx.x;
    if (tid < D) s_col[tid] = 0.f;
    __syncthreads();

    int warp = tid >> 5, lane = tid & 31;
    bool is_pair = blockIdx.x >= (N / 8);
    int row = (blockIdx.x - (is_pair ? (N / 8) : 0)) * 8 + warp;
    const float* src = is_pair ? pairn : nodes;

    float4 v = reinterpret_cast<const float4*>(src + (size_t)row * D)[lane];
    float sq = v.x * v.x + v.y * v.y + v.z * v.z + v.w * v.w;
#pragma unroll
    for (int o = 16; o > 0; o >>= 1) sq += __shfl_xor_sync(0xffffffffu, sq, o);
    float scale = 1.0f / fmaxf(sqrtf(sq), 1e-12f);
    float z0 = v.x * scale, z1 = v.y * scale, z2 = v.z * scale, z3 = v.w * scale;

    if (!is_pair) {
        __nv_bfloat162* dst = reinterpret_cast<__nv_bfloat162*>(g_zn + (size_t)row * D);
        dst[lane * 2 + 0] = __floats2bfloat162_rn(z0, z1);
        dst[lane * 2 + 1] = __floats2bfloat162_rn(z2, z3);
    }
    atomicAdd(&s_col[lane * 4 + 0], z0);
    atomicAdd(&s_col[lane * 4 + 1], z1);
    atomicAdd(&s_col[lane * 4 + 2], z2);
    atomicAdd(&s_col[lane * 4 + 3], z3);
    __syncthreads();
    if (tid < D) atomicAdd(is_pair ? &g_sumzp[tid] : &g_sumz[tid], s_col[tid]);
}

// -------- mma helpers --------
__device__ __forceinline__ void ldmx4(uint32_t r[4], uint32_t addr) {
    asm volatile("ldmatrix.sync.aligned.m8n8.x4.shared.b16 {%0,%1,%2,%3}, [%4];\n"
                 : "=r"(r[0]), "=r"(r[1]), "=r"(r[2]), "=r"(r[3]) : "r"(addr));
}
__device__ __forceinline__ void mma16816(float c[4], const uint32_t a[4], const uint32_t b[2]) {
    asm volatile("mma.sync.aligned.m16n8k16.row.col.f32.bf16.bf16.f32 "
                 "{%0,%1,%2,%3}, {%4,%5,%6,%7}, {%8,%9}, {%0,%1,%2,%3};\n"
                 : "+f"(c[0]), "+f"(c[1]), "+f"(c[2]), "+f"(c[3])
                 : "r"(a[0]), "r"(a[1]), "r"(a[2]), "r"(a[3]), "r"(b[0]), "r"(b[1]));
}

// -------- kernel 2: S = ZN @ ZN^T tile, fused exp(2s) row-sum (skip diagonal) --------
__global__ void __launch_bounds__(256, 2) simexp_kernel() {
    extern __shared__ __nv_bfloat16 smem[];
    __nv_bfloat16* sA = smem;
    __nv_bfloat16* sB = smem + BM * SSTRIDE;
    const int tid = threadIdx.x;
    const int i0 = blockIdx.y * BM;
    const int j0 = blockIdx.x * BN;

    // cooperative tile load: 128 rows x 128 bf16 each, 16B vectors, coalesced
    {
        const int r = tid >> 4;          // 0..15
        const int seg = tid & 15;        // 16B segment within a row
        const uint4* gA = reinterpret_cast<const uint4*>(g_zn + (size_t)i0 * D);
        const uint4* gB = reinterpret_cast<const uint4*>(g_zn + (size_t)j0 * D);
#pragma unroll
        for (int rr = 0; rr < 8; rr++) {
            int row = r + rr * 16;
            uint4 va = gA[row * (D / 8) + seg];
            uint4 vb = gB[row * (D / 8) + seg];
            *reinterpret_cast<uint4*>(sA + row * SSTRIDE + seg * 8) = va;
            *reinterpret_cast<uint4*>(sB + row * SSTRIDE + seg * 8) = vb;
        }
    }
    __syncthreads();

    const int warp = tid >> 5, lane = tid & 31;
    const int wm = (warp >> 1) * 32;     // warp M offset (4 warps along M)
    const int wn = (warp & 1) * 64;      // warp N offset (2 warps along N)

    float acc[2][8][4];
#pragma unroll
    for (int mt = 0; mt < 2; mt++)
#pragma unroll
        for (int nt = 0; nt < 8; nt++)
#pragma unroll
            for (int q = 0; q < 4; q++) acc[mt][nt][q] = 0.f;

    const uint32_t aBase = (uint32_t)__cvta_generic_to_shared(sA);
    const uint32_t bBase = (uint32_t)__cvta_generic_to_shared(sB);

#pragma unroll
    for (int kt = 0; kt < 8; kt++) {
        const int k0 = kt * 16;
        uint32_t afr[2][4];
#pragma unroll
        for (int mt = 0; mt < 2; mt++) {
            int row = wm + mt * 16 + (lane & 15);
            int col = k0 + (lane >> 4) * 8;
            ldmx4(afr[mt], aBase + (uint32_t)(row * SSTRIDE + col) * 2);
        }
        uint32_t bfr[8][2];
#pragma unroll
        for (int np = 0; np < 4; np++) {             // two n-tiles per x4
            int g = lane >> 3;                        // 0..3 -> (ntile parity, k half)
            int nrow = wn + np * 16 + ((g & 2) ? 8 : 0) + (lane & 7);
            int col = k0 + (g & 1) * 8;
            uint32_t r4[4];
            ldmx4(r4, bBase + (uint32_t)(nrow * SSTRIDE + col) * 2);
            bfr[np * 2 + 0][0] = r4[0]; bfr[np * 2 + 0][1] = r4[1];
            bfr[np * 2 + 1][0] = r4[2]; bfr[np * 2 + 1][1] = r4[3];
        }
#pragma unroll
        for (int mt = 0; mt < 2; mt++)
#pragma unroll
            for (int nt = 0; nt < 8; nt++)
                mma16816(acc[mt][nt], afr[mt], bfr[nt]);
    }

    // epilogue: p = sum_j exp(2*s), skip diagonal, reduce per row, one atomic
    const int rbase = i0 + wm + (lane >> 2);
    const int cbase = j0 + wn + 2 * (lane & 3);
#pragma unroll
    for (int mt = 0; mt < 2; mt++) {
#pragma unroll
        for (int half = 0; half < 2; half++) {
            int grow = rbase + mt * 16 + half * 8;
            float p = 0.f;
#pragma unroll
            for (int nt = 0; nt < 8; nt++) {
                int gc0 = cbase + nt * 8;
                float s0 = acc[mt][nt][half * 2 + 0];
                float s1 = acc[mt][nt][half * 2 + 1];
                if (grow != gc0)     p += __expf(2.0f * s0);
                if (grow != gc0 + 1) p += __expf(2.0f * s1);
            }
            p += __shfl_xor_sync(0xffffffffu, p, 1);
            p += __shfl_xor_sync(0xffffffffu, p, 2);
            if ((lane & 3) == 0) atomicAdd(&g_den[grow], p);
        }
    }
}

// -------- kernel 3: loss = sum_j log(den[j]) - (2/N) * dot(sumz, sumzp) --------
__global__ void finalize_kernel(float* __restrict__ out) {
    __shared__ float sh[256];
    int tid = threadIdx.x;
    float lg = 0.f;
    for (int i = tid; i < N; i += 256) lg += logf(g_den[i]);
    float dp = (tid < D) ? g_sumz[tid] * g_sumzp[tid] : 0.f;
    sh[tid] = lg - (2.0f / (float)N) * dp;
    __syncthreads();
    for (int s = 128; s > 0; s >>= 1) {
        if (tid < s) sh[tid] += sh[tid + s];
        __syncthreads();
    }
    if (tid == 0) out[0] = sh[0];
}

extern "C" void kernel_launch(void* const* d_in, const int* in_sizes, int n_in,
                              void* d_out, int out_size) {
    const float* nodes = (const float*)d_in[0];
    const float* pairn = (const float*)d_in[1];
    float* out = (float*)d_out;

    cudaFuncSetAttribute(simexp_kernel, cudaFuncAttributeMaxDynamicSharedMemorySize, SMEM_BYTES);

    zero_kernel<<<(N + 255) / 256, 256>>>();
    prep_kernel<<<2 * (N / 8), 256>>>(nodes, pairn);
    dim3 grid(N / BN, N / BM);
    simexp_kernel<<<grid, 256, SMEM_BYTES>>>();
    finalize_kernel<<<1, 256>>>(out);
}

// round 2
// speedup vs baseline: 1.2494x; 1.2494x over previous
#include <cuda_runtime.h>
#include <cuda_bf16.h>
#include <cstdint>

#define N 8192
#define D 128
#define BM 128
#define BN 128
#define NT_TILES 64                      // N / BM
#define NUM_TRI (NT_TILES * (NT_TILES + 1) / 2)   // 2080
#define SSTRIDE 136                      // 128 + 8 bf16 pad -> conflict-free ldmatrix
#define SMEM_BYTES (2 * BM * SSTRIDE * 2)

// -------- device scratch (no allocations allowed) --------
__device__ __nv_bfloat16 g_zn[N * D];    // normalized nodes, bf16
__device__ float g_sumz[D];              // column sum of normalized nodes
__device__ float g_sumzp[D];             // column sum of normalized pair_nodes
__device__ float g_den[N];               // den_sum per row

// -------- kernel 0: zero scratch + output --------
__global__ void zero_kernel(float* __restrict__ out) {
    int i = blockIdx.x * blockDim.x + threadIdx.x;
    if (i < N) g_den[i] = 0.f;
    if (i < D) { g_sumz[i] = 0.f; g_sumzp[i] = 0.f; }
    if (i == 0) out[0] = 0.f;
}

// -------- kernel 1: normalize rows, store bf16, accumulate column sums --------
__global__ void prep_kernel(const float* __restrict__ nodes,
                            const float* __restrict__ pairn) {
    __shared__ float s_col[D];
    int tid = threadIdx.x;
    if (tid < D) s_col[tid] = 0.f;
    __syncthreads();

    int warp = tid >> 5, lane = tid & 31;
    bool is_pair = blockIdx.x >= (N / 8);
    int row = (blockIdx.x - (is_pair ? (N / 8) : 0)) * 8 + warp;
    const float* src = is_pair ? pairn : nodes;

    float4 v = reinterpret_cast<const float4*>(src + (size_t)row * D)[lane];
    float sq = v.x * v.x + v.y * v.y + v.z * v.z + v.w * v.w;
#pragma unroll
    for (int o = 16; o > 0; o >>= 1) sq += __shfl_xor_sync(0xffffffffu, sq, o);
    float scale = 1.0f / fmaxf(sqrtf(sq), 1e-12f);
    float z0 = v.x * scale, z1 = v.y * scale, z2 = v.z * scale, z3 = v.w * scale;

    if (!is_pair) {
        __nv_bfloat162* dst = reinterpret_cast<__nv_bfloat162*>(g_zn + (size_t)row * D);
        dst[lane * 2 + 0] = __floats2bfloat162_rn(z0, z1);
        dst[lane * 2 + 1] = __floats2bfloat162_rn(z2, z3);
    }
    atomicAdd(&s_col[lane * 4 + 0], z0);
    atomicAdd(&s_col[lane * 4 + 1], z1);
    atomicAdd(&s_col[lane * 4 + 2], z2);
    atomicAdd(&s_col[lane * 4 + 3], z3);
    __syncthreads();
    if (tid < D) atomicAdd(is_pair ? &g_sumzp[tid] : &g_sumz[tid], s_col[tid]);
}

// -------- mma helpers --------
__device__ __forceinline__ void ldmx4(uint32_t r[4], uint32_t addr) {
    asm volatile("ldmatrix.sync.aligned.m8n8.x4.shared.b16 {%0,%1,%2,%3}, [%4];\n"
                 : "=r"(r[0]), "=r"(r[1]), "=r"(r[2]), "=r"(r[3]) : "r"(addr));
}
__device__ __forceinline__ void mma16816(float c[4], const uint32_t a[4], const uint32_t b[2]) {
    asm volatile("mma.sync.aligned.m16n8k16.row.col.f32.bf16.bf16.f32 "
                 "{%0,%1,%2,%3}, {%4,%5,%6,%7}, {%8,%9}, {%0,%1,%2,%3};\n"
                 : "+f"(c[0]), "+f"(c[1]), "+f"(c[2]), "+f"(c[3])
                 : "r"(a[0]), "r"(a[1]), "r"(a[2]), "r"(a[3]), "r"(b[0]), "r"(b[1]));
}

// -------- kernel 2: upper-triangular tiles of S = ZN @ ZN^T, fused exp(2s),
//          row sums always; column sums too for off-diagonal tiles (symmetry) --------
__global__ void __launch_bounds__(256, 2) simexp_kernel() {
    extern __shared__ __nv_bfloat16 smem[];
    __nv_bfloat16* sA = smem;
    __nv_bfloat16* sB = smem + BM * SSTRIDE;
    const int tid = threadIdx.x;

    // triangular decode: t -> (ti, tj), tj >= ti.  C(i) = i*(129-i)/2
    const int t = blockIdx.x;
    int ti = (int)((129.0f - sqrtf(16641.0f - 8.0f * (float)t)) * 0.5f);
    if (ti > 0 && ti * (2 * NT_TILES + 1 - ti) / 2 > t) ti--;
    while ((ti + 1) * (2 * NT_TILES + 1 - (ti + 1)) / 2 <= t) ti++;
    const int tj = ti + (t - ti * (2 * NT_TILES + 1 - ti) / 2);
    const int i0 = ti * BM;
    const int j0 = tj * BN;
    const bool offdiag = (tj != ti);

    // cooperative tile load: 128 rows x 128 bf16 each, 16B vectors, coalesced
    {
        const int r = tid >> 4;          // 0..15
        const int seg = tid & 15;        // 16B segment within a row
        const uint4* gA = reinterpret_cast<const uint4*>(g_zn + (size_t)i0 * D);
        const uint4* gB = reinterpret_cast<const uint4*>(g_zn + (size_t)j0 * D);
#pragma unroll
        for (int rr = 0; rr < 8; rr++) {
            int row = r + rr * 16;
            uint4 va = gA[row * (D / 8) + seg];
            uint4 vb = gB[row * (D / 8) + seg];
            *reinterpret_cast<uint4*>(sA + row * SSTRIDE + seg * 8) = va;
            *reinterpret_cast<uint4*>(sB + row * SSTRIDE + seg * 8) = vb;
        }
    }
    __syncthreads();

    const int warp = tid >> 5, lane = tid & 31;
    const int wm = (warp >> 1) * 32;     // warp M offset (4 warps along M)
    const int wn = (warp & 1) * 64;      // warp N offset (2 warps along N)

    float acc[2][8][4];
#pragma unroll
    for (int mt = 0; mt < 2; mt++)
#pragma unroll
        for (int nt = 0; nt < 8; nt++)
#pragma unroll
            for (int q = 0; q < 4; q++) acc[mt][nt][q] = 0.f;

    const uint32_t aBase = (uint32_t)__cvta_generic_to_shared(sA);
    const uint32_t bBase = (uint32_t)__cvta_generic_to_shared(sB);

#pragma unroll
    for (int kt = 0; kt < 8; kt++) {
        const int k0 = kt * 16;
        uint32_t afr[2][4];
#pragma unroll
        for (int mt = 0; mt < 2; mt++) {
            int row = wm + mt * 16 + (lane & 15);
            int col = k0 + (lane >> 4) * 8;
            ldmx4(afr[mt], aBase + (uint32_t)(row * SSTRIDE + col) * 2);
        }
        uint32_t bfr[8][2];
#pragma unroll
        for (int np = 0; np < 4; np++) {             // two n-tiles per x4
            int g = lane >> 3;                        // 0..3 -> (ntile parity, k half)
            int nrow = wn + np * 16 + ((g & 2) ? 8 : 0) + (lane & 7);
            int col = k0 + (g & 1) * 8;
            uint32_t r4[4];
            ldmx4(r4, bBase + (uint32_t)(nrow * SSTRIDE + col) * 2);
            bfr[np * 2 + 0][0] = r4[0]; bfr[np * 2 + 0][1] = r4[1];
            bfr[np * 2 + 1][0] = r4[2]; bfr[np * 2 + 1][1] = r4[3];
        }
#pragma unroll
        for (int mt = 0; mt < 2; mt++)
#pragma unroll
            for (int nt = 0; nt < 8; nt++)
                mma16816(acc[mt][nt], afr[mt], bfr[nt]);
    }

    // epilogue: e = exp(2*s) (diagonal entries excluded on diag tiles).
    // Row sums -> g_den[i..]; for off-diagonal tiles also column sums -> g_den[j..].
    const int rbase = i0 + wm + (lane >> 2);
    const int cbase = j0 + wn + 2 * (lane & 3);

    float ccol[8][2];
#pragma unroll
    for (int nt = 0; nt < 8; nt++) { ccol[nt][0] = 0.f; ccol[nt][1] = 0.f; }

#pragma unroll
    for (int mt = 0; mt < 2; mt++) {
#pragma unroll
        for (int half = 0; half < 2; half++) {
            int grow = rbase + mt * 16 + half * 8;
            float p = 0.f;
#pragma unroll
            for (int nt = 0; nt < 8; nt++) {
                int gc0 = cbase + nt * 8;
                float s0 = acc[mt][nt][half * 2 + 0];
                float s1 = acc[mt][nt][half * 2 + 1];
                float e0 = (grow != gc0)     ? __expf(2.0f * s0) : 0.f;
                float e1 = (grow != gc0 + 1) ? __expf(2.0f * s1) : 0.f;
                p += e0 + e1;
                ccol[nt][0] += e0;
                ccol[nt][1] += e1;
            }
            p += __shfl_xor_sync(0xffffffffu, p, 1);
            p += __shfl_xor_sync(0xffffffffu, p, 2);
            if ((lane & 3) == 0) atomicAdd(&g_den[grow], p);
        }
    }

    if (offdiag) {
#pragma unroll
        for (int nt = 0; nt < 8; nt++) {
#pragma unroll
            for (int c = 0; c < 2; c++) {
                float v = ccol[nt][c];
                v += __shfl_xor_sync(0xffffffffu, v, 4);
                v += __shfl_xor_sync(0xffffffffu, v, 8);
                v += __shfl_xor_sync(0xffffffffu, v, 16);
                if (lane < 4) atomicAdd(&g_den[j0 + wn + nt * 8 + 2 * lane + c], v);
            }
        }
    }
}

// -------- kernel 3: loss = sum_j log(den[j]) - (2/N) * dot(sumz, sumzp) --------
__global__ void finalize_kernel(float* __restrict__ out) {
    int tid = threadIdx.x;
    int i = blockIdx.x * blockDim.x + tid;
    float v = logf(g_den[i]);
    if (blockIdx.x == 0 && tid < D)
        v -= (2.0f / (float)N) * g_sumz[tid] * g_sumzp[tid];
#pragma unroll
    for (int o = 16; o > 0; o >>= 1) v += __shfl_xor_sync(0xffffffffu, v, o);
    if ((tid & 31) == 0) atomicAdd(out, v);
}

extern "C" void kernel_launch(void* const* d_in, const int* in_sizes, int n_in,
                              void* d_out, int out_size) {
    const float* nodes = (const float*)d_in[0];
    const float* pairn = (const float*)d_in[1];
    float* out = (float*)d_out;

    cudaFuncSetAttribute(simexp_kernel, cudaFuncAttributeMaxDynamicSharedMemorySize, SMEM_BYTES);

    zero_kernel<<<(N + 255) / 256, 256>>>(out);
    prep_kernel<<<2 * (N / 8), 256>>>(nodes, pairn);
    simexp_kernel<<<NUM_TRI, 256, SMEM_BYTES>>>();
    finalize_kernel<<<N / 256, 256>>>(out);
}